// round 1
// baseline (speedup 1.0000x reference)
#include <cuda_runtime.h>
#include <cuda_bf16.h>
#include <math.h>

// ---------------- problem constants ----------------
#define BATCH    2
#define SEQ      1024
#define DMODEL   1024
#define DINNER   2048
#define DSTATE   16
#define DTRANK   16
#define DCONV    4
#define MROWS    (BATCH * SEQ)          // 2048

// ---------------- scratch (device globals; no allocation allowed) ----------
__device__ float g_xres [MROWS * 2 * DINNER];   // in_proj output [m, 4096]
__device__ float g_xs   [MROWS * DINNER];       // conv+silu output
__device__ float g_xdbl [MROWS * (DTRANK + 2 * DSTATE)];  // [m, 48]
__device__ float g_delta[MROWS * DINNER];       // softplus(dt_proj)
__device__ float g_y    [MROWS * DINNER];       // gated scan output

// ---------------- SGEMM: C[M,N] = A[M,K] * W[N,K]^T + bias -----------------
// BM=BN=128, BK=16, 256 threads, 8x8 per-thread tile. M,N multiples of 128,
// K multiple of 16.
__global__ __launch_bounds__(256, 2)
void sgemm_nt(const float* __restrict__ A, const float* __restrict__ W,
              const float* __restrict__ bias, float* __restrict__ C,
              int M, int N, int K) {
    __shared__ float As[16][128];
    __shared__ float Bs[16][128];

    const int tid = threadIdx.x;
    const int bm = blockIdx.y * 128;
    const int bn = blockIdx.x * 128;
    const int tx = tid & 15;      // 0..15 -> N direction
    const int ty = tid >> 4;      // 0..15 -> M direction

    float acc[8][8];
#pragma unroll
    for (int i = 0; i < 8; i++)
#pragma unroll
        for (int j = 0; j < 8; j++) acc[i][j] = 0.f;

    for (int kt = 0; kt < K; kt += 16) {
        // cooperative loads: A tile 128x16 = 512 float4, 2 per thread
#pragma unroll
        for (int it = 0; it < 2; it++) {
            int idx = tid + it * 256;        // 0..511
            int r   = idx >> 2;              // 0..127
            int c4  = (idx & 3) << 2;        // 0,4,8,12
            float4 va = *(const float4*)(A + (size_t)(bm + r) * K + kt + c4);
            As[c4 + 0][r] = va.x; As[c4 + 1][r] = va.y;
            As[c4 + 2][r] = va.z; As[c4 + 3][r] = va.w;
            float4 vb = *(const float4*)(W + (size_t)(bn + r) * K + kt + c4);
            Bs[c4 + 0][r] = vb.x; Bs[c4 + 1][r] = vb.y;
            Bs[c4 + 2][r] = vb.z; Bs[c4 + 3][r] = vb.w;
        }
        __syncthreads();

#pragma unroll
        for (int k = 0; k < 16; k++) {
            float a[8], b[8];
            *(float4*)&a[0] = *(const float4*)&As[k][ty * 8];
            *(float4*)&a[4] = *(const float4*)&As[k][ty * 8 + 4];
            *(float4*)&b[0] = *(const float4*)&Bs[k][tx * 8];
            *(float4*)&b[4] = *(const float4*)&Bs[k][tx * 8 + 4];
#pragma unroll
            for (int i = 0; i < 8; i++)
#pragma unroll
                for (int j = 0; j < 8; j++)
                    acc[i][j] = fmaf(a[i], b[j], acc[i][j]);
        }
        __syncthreads();
    }

    // epilogue
    float bv[8];
#pragma unroll
    for (int j = 0; j < 8; j++) bv[j] = bias[bn + tx * 8 + j];
#pragma unroll
    for (int i = 0; i < 8; i++) {
        float* crow = C + (size_t)(bm + ty * 8 + i) * N + bn + tx * 8;
        float4 o0, o1;
        o0.x = acc[i][0] + bv[0]; o0.y = acc[i][1] + bv[1];
        o0.z = acc[i][2] + bv[2]; o0.w = acc[i][3] + bv[3];
        o1.x = acc[i][4] + bv[4]; o1.y = acc[i][5] + bv[5];
        o1.z = acc[i][6] + bv[6]; o1.w = acc[i][7] + bv[7];
        *(float4*)(crow)     = o0;
        *(float4*)(crow + 4) = o1;
    }
}

// ---------------- causal depthwise conv (d_conv=4) + SiLU ------------------
__global__ void conv_silu_kernel(const float* __restrict__ conv_w,
                                 const float* __restrict__ conv_b) {
    int idx = blockIdx.x * blockDim.x + threadIdx.x;   // over MROWS*DINNER
    if (idx >= MROWS * DINNER) return;
    int d = idx & (DINNER - 1);
    int m = idx >> 11;          // b*SEQ + t
    int t = m & (SEQ - 1);

    float4 w = *(const float4*)(conv_w + d * 4);
    float acc = conv_b[d];
    const float* src = g_xres + (size_t)m * (2 * DINNER) + d;  // x branch col d
    // out[t] = w0*x[t-3] + w1*x[t-2] + w2*x[t-1] + w3*x[t]
    if (t >= 3) acc = fmaf(w.x, src[-3 * 2 * DINNER], acc);
    if (t >= 2) acc = fmaf(w.y, src[-2 * 2 * DINNER], acc);
    if (t >= 1) acc = fmaf(w.z, src[-1 * 2 * DINNER], acc);
    acc = fmaf(w.w, src[0], acc);
    float s = acc / (1.f + __expf(-acc));   // SiLU
    g_xs[idx] = s;
}

// ---------------- x_proj: [M,48] = xs[M,2048] @ W[48,2048]^T + b -----------
// one warp per output element; grid (6, M), block 256 (8 warps = 8 cols)
__global__ void xproj_kernel(const float* __restrict__ W,
                             const float* __restrict__ bias) {
    int m    = blockIdx.y;
    int w    = threadIdx.x >> 5;
    int lane = threadIdx.x & 31;
    int j    = blockIdx.x * 8 + w;           // 0..47

    const float* xrow = g_xs + (size_t)m * DINNER;
    const float* wrow = W + (size_t)j * DINNER;
    float acc = 0.f;
#pragma unroll
    for (int k = lane * 4; k < DINNER; k += 128) {
        float4 a = *(const float4*)(xrow + k);
        float4 b = *(const float4*)(wrow + k);
        acc = fmaf(a.x, b.x, acc);
        acc = fmaf(a.y, b.y, acc);
        acc = fmaf(a.z, b.z, acc);
        acc = fmaf(a.w, b.w, acc);
    }
#pragma unroll
    for (int off = 16; off > 0; off >>= 1)
        acc += __shfl_xor_sync(0xffffffffu, acc, off);
    if (lane == 0) g_xdbl[(size_t)m * 48 + j] = acc + bias[j];
}

// ---------------- dt_proj (K=16) + softplus --------------------------------
// grid (8, M), block 256: each block covers 256 d's of one row m
__global__ void dt_softplus_kernel(const float* __restrict__ Wdt,
                                   const float* __restrict__ bdt) {
    __shared__ float xd[16];
    int m = blockIdx.y;
    int d = blockIdx.x * 256 + threadIdx.x;
    if (threadIdx.x < 16) xd[threadIdx.x] = g_xdbl[(size_t)m * 48 + threadIdx.x];
    __syncthreads();

    const float4* wp = (const float4*)(Wdt + (size_t)d * 16);
    float4 w0 = wp[0], w1 = wp[1], w2 = wp[2], w3 = wp[3];
    float acc = bdt[d];
    acc = fmaf(xd[0],  w0.x, acc); acc = fmaf(xd[1],  w0.y, acc);
    acc = fmaf(xd[2],  w0.z, acc); acc = fmaf(xd[3],  w0.w, acc);
    acc = fmaf(xd[4],  w1.x, acc); acc = fmaf(xd[5],  w1.y, acc);
    acc = fmaf(xd[6],  w1.z, acc); acc = fmaf(xd[7],  w1.w, acc);
    acc = fmaf(xd[8],  w2.x, acc); acc = fmaf(xd[9],  w2.y, acc);
    acc = fmaf(xd[10], w2.z, acc); acc = fmaf(xd[11], w2.w, acc);
    acc = fmaf(xd[12], w3.x, acc); acc = fmaf(xd[13], w3.y, acc);
    acc = fmaf(xd[14], w3.z, acc); acc = fmaf(xd[15], w3.w, acc);
    float sp = (acc > 20.f) ? acc : log1pf(__expf(acc));
    g_delta[(size_t)m * DINNER + d] = sp;
}

// ---------------- selective scan + skip + gating ---------------------------
// thread t handles one (channel c, state n): n = tid&15, c = tid>>4
// c = b*DINNER + d. 65536 threads total.
__global__ void scan_kernel(const float* __restrict__ A_log,
                            const float* __restrict__ Dp) {
    int tid = blockIdx.x * blockDim.x + threadIdx.x;
    int n = tid & 15;
    int c = tid >> 4;                 // 0..4095
    int d = c & (DINNER - 1);
    int b = c >> 11;

    float Aval = -__expf(A_log[d * DSTATE + n]);
    float Dv   = Dp[d];

    const float* dptr  = g_delta + (size_t)b * SEQ * DINNER + d;
    const float* xptr  = g_xs    + (size_t)b * SEQ * DINNER + d;
    const float* rptr  = g_xres  + (size_t)b * SEQ * (2 * DINNER) + DINNER + d;
    const float* bcptr = g_xdbl  + (size_t)b * SEQ * 48 + DTRANK + n;
    float*       yptr  = g_y     + (size_t)b * SEQ * DINNER + d;

    float h = 0.f;
    for (int t = 0; t < SEQ; t++) {
        float dt = __ldg(dptr);
        float xv = __ldg(xptr);
        float Bv = __ldg(bcptr);
        float Cv = __ldg(bcptr + DSTATE);

        float dA = __expf(dt * Aval);
        h = fmaf(dA, h, dt * xv * Bv);
        float p = h * Cv;
        p += __shfl_xor_sync(0xffffffffu, p, 1);
        p += __shfl_xor_sync(0xffffffffu, p, 2);
        p += __shfl_xor_sync(0xffffffffu, p, 4);
        p += __shfl_xor_sync(0xffffffffu, p, 8);

        if (n == 0) {
            float r = __ldg(rptr);
            float g = r / (1.f + __expf(-r));
            *yptr = (p + xv * Dv) * g;
        }
        dptr += DINNER; xptr += DINNER; rptr += 2 * DINNER;
        bcptr += 48;    yptr += DINNER;
    }
}

// ---------------- launch ----------------------------------------------------
extern "C" void kernel_launch(void* const* d_in, const int* in_sizes, int n_in,
                              void* d_out, int out_size) {
    const float* x        = (const float*)d_in[0];
    const float* in_w     = (const float*)d_in[1];
    const float* in_b     = (const float*)d_in[2];
    const float* conv_w   = (const float*)d_in[3];
    const float* conv_b   = (const float*)d_in[4];
    const float* xproj_w  = (const float*)d_in[5];
    const float* xproj_b  = (const float*)d_in[6];
    const float* dt_w     = (const float*)d_in[7];
    const float* dt_b     = (const float*)d_in[8];
    const float* A_log    = (const float*)d_in[9];
    const float* Dp       = (const float*)d_in[10];
    const float* out_w    = (const float*)d_in[11];
    const float* out_b    = (const float*)d_in[12];
    float* out = (float*)d_out;

    float *p_xres, *p_y;
    cudaGetSymbolAddress((void**)&p_xres, g_xres);
    cudaGetSymbolAddress((void**)&p_y, g_y);

    // 1) in_proj: [2048, 4096] = x[2048,1024] @ in_w[4096,1024]^T
    {
        dim3 grid(2 * DINNER / 128, MROWS / 128);
        sgemm_nt<<<grid, 256>>>(x, in_w, in_b, p_xres, MROWS, 2 * DINNER, DMODEL);
    }
    // 2) conv + silu
    {
        int total = MROWS * DINNER;
        conv_silu_kernel<<<(total + 255) / 256, 256>>>(conv_w, conv_b);
    }
    // 3) x_proj -> [2048, 48]
    {
        dim3 grid(6, MROWS);
        xproj_kernel<<<grid, 256>>>(xproj_w, xproj_b);
    }
    // 4) dt_proj + softplus -> delta [2048, 2048]
    {
        dim3 grid(8, MROWS);
        dt_softplus_kernel<<<grid, 256>>>(dt_w, dt_b);
    }
    // 5) selective scan + skip + gating -> g_y
    {
        scan_kernel<<<(BATCH * DINNER * DSTATE) / 256, 256>>>(A_log, Dp);
    }
    // 6) out_proj: [2048, 1024] = y[2048,2048] @ out_w[1024,2048]^T
    {
        dim3 grid(DMODEL / 128, MROWS / 128);
        sgemm_nt<<<grid, 256>>>(p_y, out_w, out_b, out, MROWS, DMODEL, DINNER);
    }
}

// round 2
// speedup vs baseline: 1.4700x; 1.4700x over previous
#include <cuda_runtime.h>
#include <cuda_bf16.h>
#include <math.h>
#include <stdint.h>

// ---------------- problem constants ----------------
#define BATCH    2
#define SEQ      1024
#define DMODEL   1024
#define DINNER   2048
#define DSTATE   16
#define DTRANK   16
#define DCONV    4
#define MROWS    (BATCH * SEQ)          // 2048

// ---------------- scratch ----------------
__device__ float g_xres [MROWS * 2 * DINNER];
__device__ float g_xs   [MROWS * DINNER];
__device__ float g_xdbl [MROWS * (DTRANK + 2 * DSTATE)];
__device__ float g_delta[MROWS * DINNER];
__device__ float g_y    [MROWS * DINNER];

// ---------------- TF32 tensor-core GEMM -------------------------------------
// C[M,N] = A[M,K] @ W[N,K]^T + bias.  BM=BN=128, BK=32, 256 thr (8 warps).
// Warp tile 64(M) x 32(N) via mma.sync.m16n8k8.tf32.
#define SSTR 36   // shared stride (floats) -> conflict-free fragment loads

__device__ __forceinline__ uint32_t f2tf32(float f) {
    uint32_t u;
    asm("cvt.rna.tf32.f32 %0, %1;" : "=r"(u) : "f"(f));
    return u;
}

__global__ __launch_bounds__(256)
void gemm_tf32(const float* __restrict__ A, const float* __restrict__ W,
               const float* __restrict__ bias, float* __restrict__ C,
               int M, int N, int K) {
    __shared__ uint32_t As[128 * SSTR];
    __shared__ uint32_t Bs[128 * SSTR];

    const int tid  = threadIdx.x;
    const int lane = tid & 31;
    const int wid  = tid >> 5;
    const int wm   = (wid & 1) * 64;     // warp M offset
    const int wn   = (wid >> 1) * 32;    // warp N offset
    const int grp  = lane >> 2;
    const int tig  = lane & 3;
    const int bm   = blockIdx.y * 128;
    const int bn   = blockIdx.x * 128;

    float c[4][4][4];
#pragma unroll
    for (int i = 0; i < 4; i++)
#pragma unroll
        for (int j = 0; j < 4; j++)
#pragma unroll
            for (int q = 0; q < 4; q++) c[i][j][q] = 0.f;

    const int nt = K >> 5;   // K/32 iterations
    float4 sa[4], sb[4];

    // prologue loads for kt = 0
#pragma unroll
    for (int i = 0; i < 4; i++) {
        int lin = tid + i * 256;
        int r   = lin >> 3;
        int kq  = (lin & 7) << 2;
        sa[i] = *(const float4*)(A + (size_t)(bm + r) * K + kq);
        sb[i] = *(const float4*)(W + (size_t)(bn + r) * K + kq);
    }

    for (int kt = 0; kt < nt; kt++) {
        __syncthreads();
        // store staged tile (as tf32 bits)
#pragma unroll
        for (int i = 0; i < 4; i++) {
            int lin = tid + i * 256;
            int r   = lin >> 3;
            int kq  = (lin & 7) << 2;
            uint32_t* pa = &As[r * SSTR + kq];
            pa[0] = f2tf32(sa[i].x); pa[1] = f2tf32(sa[i].y);
            pa[2] = f2tf32(sa[i].z); pa[3] = f2tf32(sa[i].w);
            uint32_t* pb = &Bs[r * SSTR + kq];
            pb[0] = f2tf32(sb[i].x); pb[1] = f2tf32(sb[i].y);
            pb[2] = f2tf32(sb[i].z); pb[3] = f2tf32(sb[i].w);
        }
        __syncthreads();

        // issue next tile's global loads (overlaps with compute below)
        if (kt + 1 < nt) {
            int koff = (kt + 1) << 5;
#pragma unroll
            for (int i = 0; i < 4; i++) {
                int lin = tid + i * 256;
                int r   = lin >> 3;
                int kq  = (lin & 7) << 2;
                sa[i] = *(const float4*)(A + (size_t)(bm + r) * K + koff + kq);
                sb[i] = *(const float4*)(W + (size_t)(bn + r) * K + koff + kq);
            }
        }

        // compute: 4 k-steps of 8
#pragma unroll
        for (int ks = 0; ks < 4; ks++) {
            int k0 = ks * 8;
            uint32_t a[4][4], b[4][2];
#pragma unroll
            for (int mi = 0; mi < 4; mi++) {
                int mr = wm + mi * 16;
                a[mi][0] = As[(mr + grp)     * SSTR + k0 + tig];
                a[mi][1] = As[(mr + grp + 8) * SSTR + k0 + tig];
                a[mi][2] = As[(mr + grp)     * SSTR + k0 + tig + 4];
                a[mi][3] = As[(mr + grp + 8) * SSTR + k0 + tig + 4];
            }
#pragma unroll
            for (int nj = 0; nj < 4; nj++) {
                int nr = wn + nj * 8 + grp;
                b[nj][0] = Bs[nr * SSTR + k0 + tig];
                b[nj][1] = Bs[nr * SSTR + k0 + tig + 4];
            }
#pragma unroll
            for (int mi = 0; mi < 4; mi++)
#pragma unroll
                for (int nj = 0; nj < 4; nj++) {
                    asm volatile(
                        "mma.sync.aligned.m16n8k8.row.col.f32.tf32.tf32.f32 "
                        "{%0,%1,%2,%3},{%4,%5,%6,%7},{%8,%9},{%0,%1,%2,%3};\n"
                        : "+f"(c[mi][nj][0]), "+f"(c[mi][nj][1]),
                          "+f"(c[mi][nj][2]), "+f"(c[mi][nj][3])
                        : "r"(a[mi][0]), "r"(a[mi][1]), "r"(a[mi][2]), "r"(a[mi][3]),
                          "r"(b[nj][0]), "r"(b[nj][1]));
                }
        }
    }

    // epilogue: bias + store
#pragma unroll
    for (int nj = 0; nj < 4; nj++) {
        int n = bn + wn + nj * 8 + tig * 2;
        float bv0 = bias[n], bv1 = bias[n + 1];
#pragma unroll
        for (int mi = 0; mi < 4; mi++) {
            int m = bm + wm + mi * 16 + grp;
            float2 v0 = make_float2(c[mi][nj][0] + bv0, c[mi][nj][1] + bv1);
            float2 v1 = make_float2(c[mi][nj][2] + bv0, c[mi][nj][3] + bv1);
            *(float2*)(C + (size_t)m * N + n)       = v0;
            *(float2*)(C + (size_t)(m + 8) * N + n) = v1;
        }
    }
}

// ---------------- causal depthwise conv (d_conv=4) + SiLU ------------------
__global__ void conv_silu_kernel(const float* __restrict__ conv_w,
                                 const float* __restrict__ conv_b) {
    int idx = blockIdx.x * blockDim.x + threadIdx.x;
    if (idx >= MROWS * DINNER) return;
    int d = idx & (DINNER - 1);
    int m = idx >> 11;
    int t = m & (SEQ - 1);

    float4 w = *(const float4*)(conv_w + d * 4);
    float acc = conv_b[d];
    const float* src = g_xres + (size_t)m * (2 * DINNER) + d;
    if (t >= 3) acc = fmaf(w.x, src[-3 * 2 * DINNER], acc);
    if (t >= 2) acc = fmaf(w.y, src[-2 * 2 * DINNER], acc);
    if (t >= 1) acc = fmaf(w.z, src[-1 * 2 * DINNER], acc);
    acc = fmaf(w.w, src[0], acc);
    g_xs[idx] = acc / (1.f + __expf(-acc));
}

// ---------------- x_proj: [M,48] = xs[M,2048] @ W[48,2048]^T + b -----------
// grid (6, MROWS/16), block 256: warp w -> column j = bx*8+w, handles 16 rows.
// W row cached in 64 registers per lane.
__global__ __launch_bounds__(256)
void xproj_kernel(const float* __restrict__ W,
                  const float* __restrict__ bias) {
    int lane = threadIdx.x & 31;
    int j    = blockIdx.x * 8 + (threadIdx.x >> 5);
    int m0   = blockIdx.y * 16;

    const float* wrow = W + (size_t)j * DINNER;
    float wr[64];
#pragma unroll
    for (int i = 0; i < 16; i++) {
        float4 v = *(const float4*)(wrow + lane * 4 + i * 128);
        wr[i * 4 + 0] = v.x; wr[i * 4 + 1] = v.y;
        wr[i * 4 + 2] = v.z; wr[i * 4 + 3] = v.w;
    }
    float bj = bias[j];

    for (int mi = 0; mi < 16; mi++) {
        const float* xrow = g_xs + (size_t)(m0 + mi) * DINNER;
        float acc = 0.f;
#pragma unroll
        for (int i = 0; i < 16; i++) {
            float4 x = *(const float4*)(xrow + lane * 4 + i * 128);
            acc = fmaf(x.x, wr[i * 4 + 0], acc);
            acc = fmaf(x.y, wr[i * 4 + 1], acc);
            acc = fmaf(x.z, wr[i * 4 + 2], acc);
            acc = fmaf(x.w, wr[i * 4 + 3], acc);
        }
#pragma unroll
        for (int off = 16; off > 0; off >>= 1)
            acc += __shfl_xor_sync(0xffffffffu, acc, off);
        if (lane == 0) g_xdbl[(size_t)(m0 + mi) * 48 + j] = acc + bj;
    }
}

// ---------------- dt_proj (K=16) + softplus --------------------------------
// grid (DINNER/256, MROWS/32): block owns 256 d's, processes 32 m rows.
// W row (16 floats) cached in registers; xd tile staged in shared.
__global__ __launch_bounds__(256)
void dt_softplus_kernel(const float* __restrict__ Wdt,
                        const float* __restrict__ bdt) {
    __shared__ float xd[32][16];
    int d  = blockIdx.x * 256 + threadIdx.x;
    int m0 = blockIdx.y * 32;

    float w[16];
#pragma unroll
    for (int i = 0; i < 4; i++) {
        float4 v = *(const float4*)(Wdt + (size_t)d * 16 + i * 4);
        w[i * 4 + 0] = v.x; w[i * 4 + 1] = v.y;
        w[i * 4 + 2] = v.z; w[i * 4 + 3] = v.w;
    }
    float bias = bdt[d];

#pragma unroll
    for (int it = 0; it < 2; it++) {
        int lin = threadIdx.x + it * 256;   // 0..511
        int mi  = lin >> 4;
        int r   = lin & 15;
        xd[mi][r] = g_xdbl[(size_t)(m0 + mi) * 48 + r];
    }
    __syncthreads();

    for (int mi = 0; mi < 32; mi++) {
        float acc = bias;
#pragma unroll
        for (int r = 0; r < 16; r++) acc = fmaf(xd[mi][r], w[r], acc);
        float sp = (acc > 20.f) ? acc : log1pf(__expf(acc));
        g_delta[(size_t)(m0 + mi) * DINNER + d] = sp;
    }
}

// ---------------- selective scan + skip + gating ---------------------------
__global__ void scan_kernel(const float* __restrict__ A_log,
                            const float* __restrict__ Dp) {
    int tid = blockIdx.x * blockDim.x + threadIdx.x;
    int n = tid & 15;
    int c = tid >> 4;
    int d = c & (DINNER - 1);
    int b = c >> 11;

    float Aval = -__expf(A_log[d * DSTATE + n]);
    float Dv   = Dp[d];

    const float* dptr  = g_delta + (size_t)b * SEQ * DINNER + d;
    const float* xptr  = g_xs    + (size_t)b * SEQ * DINNER + d;
    const float* rptr  = g_xres  + (size_t)b * SEQ * (2 * DINNER) + DINNER + d;
    const float* bcptr = g_xdbl  + (size_t)b * SEQ * 48 + DTRANK + n;
    float*       yptr  = g_y     + (size_t)b * SEQ * DINNER + d;

    float h = 0.f;
    for (int t = 0; t < SEQ; t++) {
        float dt = __ldg(dptr);
        float xv = __ldg(xptr);
        float Bv = __ldg(bcptr);
        float Cv = __ldg(bcptr + DSTATE);

        float dA = __expf(dt * Aval);
        h = fmaf(dA, h, dt * xv * Bv);
        float p = h * Cv;
        p += __shfl_xor_sync(0xffffffffu, p, 1);
        p += __shfl_xor_sync(0xffffffffu, p, 2);
        p += __shfl_xor_sync(0xffffffffu, p, 4);
        p += __shfl_xor_sync(0xffffffffu, p, 8);

        if (n == 0) {
            float r = __ldg(rptr);
            float g = r / (1.f + __expf(-r));
            *yptr = (p + xv * Dv) * g;
        }
        dptr += DINNER; xptr += DINNER; rptr += 2 * DINNER;
        bcptr += 48;    yptr += DINNER;
    }
}

// ---------------- launch ----------------------------------------------------
extern "C" void kernel_launch(void* const* d_in, const int* in_sizes, int n_in,
                              void* d_out, int out_size) {
    const float* x        = (const float*)d_in[0];
    const float* in_w     = (const float*)d_in[1];
    const float* in_b     = (const float*)d_in[2];
    const float* conv_w   = (const float*)d_in[3];
    const float* conv_b   = (const float*)d_in[4];
    const float* xproj_w  = (const float*)d_in[5];
    const float* xproj_b  = (const float*)d_in[6];
    const float* dt_w     = (const float*)d_in[7];
    const float* dt_b     = (const float*)d_in[8];
    const float* A_log    = (const float*)d_in[9];
    const float* Dp       = (const float*)d_in[10];
    const float* out_w    = (const float*)d_in[11];
    const float* out_b    = (const float*)d_in[12];
    float* out = (float*)d_out;

    float *p_xres, *p_y;
    cudaGetSymbolAddress((void**)&p_xres, g_xres);
    cudaGetSymbolAddress((void**)&p_y, g_y);

    // 1) in_proj: [2048, 4096]
    {
        dim3 grid(2 * DINNER / 128, MROWS / 128);
        gemm_tf32<<<grid, 256>>>(x, in_w, in_b, p_xres, MROWS, 2 * DINNER, DMODEL);
    }
    // 2) conv + silu
    {
        int total = MROWS * DINNER;
        conv_silu_kernel<<<(total + 255) / 256, 256>>>(conv_w, conv_b);
    }
    // 3) x_proj -> [2048, 48]
    {
        dim3 grid(6, MROWS / 16);
        xproj_kernel<<<grid, 256>>>(xproj_w, xproj_b);
    }
    // 4) dt_proj + softplus
    {
        dim3 grid(DINNER / 256, MROWS / 32);
        dt_softplus_kernel<<<grid, 256>>>(dt_w, dt_b);
    }
    // 5) selective scan + skip + gating
    {
        scan_kernel<<<(BATCH * DINNER * DSTATE) / 256, 256>>>(A_log, Dp);
    }
    // 6) out_proj: [2048, 1024]
    {
        dim3 grid(DMODEL / 128, MROWS / 128);
        gemm_tf32<<<grid, 256>>>(p_y, out_w, out_b, out, MROWS, DMODEL, DINNER);
    }
}